// round 4
// baseline (speedup 1.0000x reference)
#include <cuda_runtime.h>

#define BB 256
#define TT 1024
#define IDIM 2
#define HH 128
#define LL 4
#define MTOT (BB * TT)  // 262144

// Scratch (device globals: allocation-free). h ping-pong + xp stream.
__device__ float g_h0[BB * TT * HH];
__device__ float g_h1[BB * TT * HH];
__device__ float g_xp[BB * TT * HH];

typedef unsigned long long ull;

__device__ __forceinline__ void ffma2(ull& acc, ull a, ull b) {
    asm("fma.rn.f32x2 %0, %1, %2, %0;" : "+l"(acc) : "l"(a), "l"(b));
}
__device__ __forceinline__ ull add2(ull a, ull b) {
    ull d;
    asm("add.rn.f32x2 %0, %1, %2;" : "=l"(d) : "l"(a), "l"(b));
    return d;
}
__device__ __forceinline__ ull dup2(float a) {
    ull d;
    asm("mov.b64 %0, {%1, %1};" : "=l"(d) : "f"(a));
    return d;
}
__device__ __forceinline__ ull pack2(float x, float y) {
    ull d;
    asm("mov.b64 %0, {%1, %2};" : "=l"(d) : "f"(x), "f"(y));
    return d;
}

// ---------------- layer-0 input projection (I=2, trivial) ----------------
__global__ void proj0_kernel(const float* __restrict__ x,
                             const float* __restrict__ W0,
                             const float* __restrict__ bih,
                             const float* __restrict__ bhh,
                             float* __restrict__ xp) {
    int idx = blockIdx.x * 256 + threadIdx.x;
    int m = idx >> 7, j = idx & 127;
    float2 xv = *(const float2*)(x + m * 2);
    float2 w = *(const float2*)(W0 + j * 2);
    xp[idx] = fmaf(xv.x, w.x, fmaf(xv.y, w.y, bih[j] + bhh[j]));
}

// ---------------- input-projection GEMM for layers 1..3 ----------------
// xp[m, n] = sum_k A[m, k] * W[n, k] + bih[n] + bhh[n]
// M = 262144, N = K = 128. CTA tile 128(M) x 128(N), K staged in 16-chunks,
// double-buffered smem, 8x8 outputs/thread as f32x2 n-pairs.
__global__ void __launch_bounds__(256, 2)
gemm_xp(const float* __restrict__ A, const float* __restrict__ W,
        const float* __restrict__ bih, const float* __restrict__ bhh,
        float* __restrict__ xp) {
    __shared__ float As[2][128][17];   // [m][k-within-chunk], pad 17
    __shared__ float Bs[2][16][132];   // [k][n], pad 132 keeps 16B row align

    const int tid = threadIdx.x;
    const int m0 = blockIdx.x * 128;
    const int tx = tid & 15, ty = tid >> 4;
    const int n0 = tx * 8, mt = ty * 8;

    float4 av[2], bv[2];
    // load chunk 0
#pragma unroll
    for (int it = 0; it < 2; it++) {
        int idx = tid + it * 256;
        int mm = idx >> 2, kq = idx & 3;
        av[it] = *(const float4*)(A + (size_t)(m0 + mm) * HH + kq * 4);
        bv[it] = *(const float4*)(W + (size_t)mm * HH + kq * 4);
    }
#pragma unroll
    for (int it = 0; it < 2; it++) {
        int idx = tid + it * 256;
        int mm = idx >> 2, kq = idx & 3;
        As[0][mm][kq * 4 + 0] = av[it].x;
        As[0][mm][kq * 4 + 1] = av[it].y;
        As[0][mm][kq * 4 + 2] = av[it].z;
        As[0][mm][kq * 4 + 3] = av[it].w;
        Bs[0][kq * 4 + 0][mm] = bv[it].x;
        Bs[0][kq * 4 + 1][mm] = bv[it].y;
        Bs[0][kq * 4 + 2][mm] = bv[it].z;
        Bs[0][kq * 4 + 3][mm] = bv[it].w;
    }
    __syncthreads();

    ull acc[8][4];
#pragma unroll
    for (int i = 0; i < 8; i++)
#pragma unroll
        for (int p = 0; p < 4; p++) acc[i][p] = 0ULL;

    int buf = 0;
    for (int kc = 0; kc < 8; kc++) {
        if (kc < 7) {  // prefetch next chunk into registers
#pragma unroll
            for (int it = 0; it < 2; it++) {
                int idx = tid + it * 256;
                int mm = idx >> 2, kq = idx & 3;
                av[it] = *(const float4*)(A + (size_t)(m0 + mm) * HH +
                                          (kc + 1) * 16 + kq * 4);
                bv[it] = *(const float4*)(W + (size_t)mm * HH + (kc + 1) * 16 +
                                          kq * 4);
            }
        }
#pragma unroll
        for (int k = 0; k < 16; k++) {
            const ulonglong2* bp = (const ulonglong2*)&Bs[buf][k][n0];
            ulonglong2 u0 = bp[0], u1 = bp[1];
            ull ad[8];
#pragma unroll
            for (int i = 0; i < 8; i++) ad[i] = dup2(As[buf][mt + i][k]);
#pragma unroll
            for (int i = 0; i < 8; i++) {
                ffma2(acc[i][0], ad[i], u0.x);
                ffma2(acc[i][1], ad[i], u0.y);
                ffma2(acc[i][2], ad[i], u1.x);
                ffma2(acc[i][3], ad[i], u1.y);
            }
        }
        if (kc < 7) {
#pragma unroll
            for (int it = 0; it < 2; it++) {
                int idx = tid + it * 256;
                int mm = idx >> 2, kq = idx & 3;
                As[buf ^ 1][mm][kq * 4 + 0] = av[it].x;
                As[buf ^ 1][mm][kq * 4 + 1] = av[it].y;
                As[buf ^ 1][mm][kq * 4 + 2] = av[it].z;
                As[buf ^ 1][mm][kq * 4 + 3] = av[it].w;
                Bs[buf ^ 1][kq * 4 + 0][mm] = bv[it].x;
                Bs[buf ^ 1][kq * 4 + 1][mm] = bv[it].y;
                Bs[buf ^ 1][kq * 4 + 2][mm] = bv[it].z;
                Bs[buf ^ 1][kq * 4 + 3][mm] = bv[it].w;
            }
            __syncthreads();
            buf ^= 1;
        }
    }

    // epilogue: bias + store (f32x2 packed, 2x STG.128 per m-row)
    ull biasp[4];
#pragma unroll
    for (int p = 0; p < 4; p++) {
        float b0 = bih[n0 + 2 * p] + bhh[n0 + 2 * p];
        float b1 = bih[n0 + 2 * p + 1] + bhh[n0 + 2 * p + 1];
        biasp[p] = pack2(b0, b1);
    }
#pragma unroll
    for (int i = 0; i < 8; i++) {
        ull o0 = add2(acc[i][0], biasp[0]);
        ull o1 = add2(acc[i][1], biasp[1]);
        ull o2 = add2(acc[i][2], biasp[2]);
        ull o3 = add2(acc[i][3], biasp[3]);
        float* dst = xp + (size_t)(m0 + mt + i) * HH + n0;
        *(ulonglong2*)dst = make_ulonglong2(o0, o1);
        *(ulonglong2*)(dst + 4) = make_ulonglong2(o2, o3);
    }
}

// ---------------- recurrent scan (one layer) ----------------
// h[t] = relu(xp[t] + Whh @ h[t-1]); xp precomputed (includes biases).
// 512 threads: tid = (j<<2) | (s<<1) | r ; j = output unit, s = k-half,
// r = batch row. Cross-half reduce via shfl_xor(2) (same warp). One
// __syncthreads per step using double-buffered h.
__global__ void __launch_bounds__(512, 1)
rnn_scan(const float* __restrict__ xp, float* __restrict__ out_h,
         const float* __restrict__ Whh) {
    __shared__ __align__(16) float hbuf[2][2][136];  // [buf][r][s*68 + idx]

    const int tid = threadIdx.x;
    const int r = tid & 1;
    const int s = (tid >> 1) & 1;
    const int j = tid >> 2;
    const int b = blockIdx.x * 2 + r;

    // weights: Whh[j, s*64 .. s*64+63] as 32 packed f32x2 pairs
    ull w[32];
    {
        const ull* wp = (const ull*)(Whh + j * HH + s * 64);
#pragma unroll
        for (int i = 0; i < 32; i++) w[i] = wp[i];
    }

    for (int i = tid; i < 544; i += 512) ((float*)hbuf)[i] = 0.f;

    const bool wr = (s == 0);
    const float* xptr = xp + (size_t)b * TT * HH + j;
    float* optr = out_h + (size_t)b * TT * HH + j;
    float xpA = 0.f, xpB = 0.f;
    if (wr) {
        xpA = xptr[0];
        xpB = xptr[HH];
    }
    const float* xpf = xptr + 2 * HH;
    __syncthreads();

    int buf = 0;
    for (int t = 0; t < TT; t++) {
        // distance-2 xp prefetch (covers ~600cyc LDG latency)
        float xpC = 0.f;
        if (wr && t + 2 < TT) xpC = __ldg(xpf);
        xpf += HH;

        const ulonglong2* hp = (const ulonglong2*)&hbuf[buf][r][s * 68];
        ull a0 = 0ULL, a1 = 0ULL, a2 = 0ULL, a3 = 0ULL;
#pragma unroll
        for (int q = 0; q < 16; q += 2) {
            ulonglong2 u = hp[q];
            ffma2(a0, u.x, w[2 * q]);
            ffma2(a1, u.y, w[2 * q + 1]);
            ulonglong2 v = hp[q + 1];
            ffma2(a2, v.x, w[2 * q + 2]);
            ffma2(a3, v.y, w[2 * q + 3]);
        }
        ull sA = add2(add2(a0, a2), add2(a1, a3));
        float2 f = *(float2*)&sA;
        float sum = f.x + f.y;
        sum += __shfl_xor_sync(0xffffffffu, sum, 2);  // combine k-halves
        float h = fmaxf(sum + xpA, 0.f);
        if (wr) {
            int ofs = (j < 64) ? j : j + 4;  // half offset 68 (swizzle pad)
            hbuf[buf ^ 1][r][ofs] = h;
            optr[t * HH] = h;
            xpA = xpB;
            xpB = xpC;
        }
        buf ^= 1;
        __syncthreads();
    }
}

// ---------------- FC on last timestep ----------------
__global__ void fc_kernel(const float* __restrict__ h,
                          const float* __restrict__ fcw,
                          const float* __restrict__ fcb,
                          float* __restrict__ out) {
    int b = blockIdx.x;
    int k = threadIdx.x;
    float v = h[(size_t)b * (TT * HH) + (TT - 1) * HH + k] * fcw[k];
#pragma unroll
    for (int o = 16; o > 0; o >>= 1) v += __shfl_down_sync(0xffffffffu, v, o);
    __shared__ float sred[4];
    if ((k & 31) == 0) sred[k >> 5] = v;
    __syncthreads();
    if (k == 0) out[b] = sred[0] + sred[1] + sred[2] + sred[3] + fcb[0];
}

extern "C" void kernel_launch(void* const* d_in, const int* in_sizes, int n_in,
                              void* d_out, int out_size) {
    const float* x    = (const float*)d_in[0];  // [B,T,I]
    const float* Wih0 = (const float*)d_in[1];  // [H,I]
    const float* WihL = (const float*)d_in[2];  // [L-1,H,H]
    const float* Whh  = (const float*)d_in[3];  // [L,H,H]
    const float* bih  = (const float*)d_in[4];  // [L,H]
    const float* bhh  = (const float*)d_in[5];  // [L,H]
    const float* fcw  = (const float*)d_in[6];  // [C,H]
    const float* fcb  = (const float*)d_in[7];  // [C]
    float* out = (float*)d_out;                 // [B,C] = [256,1]

    float *h0, *h1, *xpb;
    cudaGetSymbolAddress((void**)&h0, g_h0);
    cudaGetSymbolAddress((void**)&h1, g_h1);
    cudaGetSymbolAddress((void**)&xpb, g_xp);

    const int HW = HH * HH;
    // layer 0
    proj0_kernel<<<(MTOT * HH) / 256, 256>>>(x, Wih0, bih, bhh, xpb);
    rnn_scan<<<BB / 2, 512>>>(xpb, h0, Whh + 0 * HW);
    // layer 1
    gemm_xp<<<MTOT / 128, 256>>>(h0, WihL + 0 * HW, bih + 1 * HH, bhh + 1 * HH,
                                 xpb);
    rnn_scan<<<BB / 2, 512>>>(xpb, h1, Whh + 1 * HW);
    // layer 2
    gemm_xp<<<MTOT / 128, 256>>>(h1, WihL + 1 * HW, bih + 2 * HH, bhh + 2 * HH,
                                 xpb);
    rnn_scan<<<BB / 2, 512>>>(xpb, h0, Whh + 2 * HW);
    // layer 3
    gemm_xp<<<MTOT / 128, 256>>>(h0, WihL + 2 * HW, bih + 3 * HH, bhh + 3 * HH,
                                 xpb);
    rnn_scan<<<BB / 2, 512>>>(xpb, h1, Whh + 3 * HW);
    // fc
    fc_kernel<<<BB, HH>>>(h1, fcw, fcb, out);
}

// round 5
// speedup vs baseline: 1.7760x; 1.7760x over previous
#include <cuda_runtime.h>

#define BB 256
#define TT 1024
#define IDIM 2
#define HH 128
#define LL 4
#define MTOT (BB * TT)  // 262144

// Scratch (device globals: allocation-free). h ping-pong + xp stream.
// g_xp padded by 4 rows for the distance-3 register-ring prefetch overrun.
__device__ float g_h0[BB * TT * HH];
__device__ float g_h1[BB * TT * HH];
__device__ float g_xp[BB * TT * HH + 4 * HH];

typedef unsigned long long ull;

__device__ __forceinline__ void ffma2(ull& acc, ull a, ull b) {
    asm("fma.rn.f32x2 %0, %1, %2, %0;" : "+l"(acc) : "l"(a), "l"(b));
}
__device__ __forceinline__ ull add2(ull a, ull b) {
    ull d;
    asm("add.rn.f32x2 %0, %1, %2;" : "=l"(d) : "l"(a), "l"(b));
    return d;
}
__device__ __forceinline__ ull dup2(float a) {
    ull d;
    asm("mov.b64 %0, {%1, %1};" : "=l"(d) : "f"(a));
    return d;
}
__device__ __forceinline__ ull pack2(float x, float y) {
    ull d;
    asm("mov.b64 %0, {%1, %2};" : "=l"(d) : "f"(x), "f"(y));
    return d;
}

// ---------------- layer-0 input projection (I=2, trivial) ----------------
__global__ void proj0_kernel(const float* __restrict__ x,
                             const float* __restrict__ W0,
                             const float* __restrict__ bih,
                             const float* __restrict__ bhh,
                             float* __restrict__ xp) {
    int idx = blockIdx.x * 256 + threadIdx.x;
    int m = idx >> 7, j = idx & 127;
    float2 xv = *(const float2*)(x + m * 2);
    float2 w = *(const float2*)(W0 + j * 2);
    xp[idx] = fmaf(xv.x, w.x, fmaf(xv.y, w.y, bih[j] + bhh[j]));
}

// ---------------- input-projection GEMM for layers 1..3 ----------------
// xp[m, n] = sum_k A[m, k] * W[n, k] + bih[n] + bhh[n]
// M = 262144, N = K = 128. CTA tile 128(M) x 128(N), K staged in 16-chunks,
// double-buffered smem, 8x8 outputs/thread as f32x2 n-pairs.
__global__ void __launch_bounds__(256, 2)
gemm_xp(const float* __restrict__ A, const float* __restrict__ W,
        const float* __restrict__ bih, const float* __restrict__ bhh,
        float* __restrict__ xp) {
    __shared__ float As[2][128][17];
    __shared__ float Bs[2][16][132];

    const int tid = threadIdx.x;
    const int m0 = blockIdx.x * 128;
    const int tx = tid & 15, ty = tid >> 4;
    const int n0 = tx * 8, mt = ty * 8;

    float4 av[2], bv[2];
#pragma unroll
    for (int it = 0; it < 2; it++) {
        int idx = tid + it * 256;
        int mm = idx >> 2, kq = idx & 3;
        av[it] = *(const float4*)(A + (size_t)(m0 + mm) * HH + kq * 4);
        bv[it] = *(const float4*)(W + (size_t)mm * HH + kq * 4);
    }
#pragma unroll
    for (int it = 0; it < 2; it++) {
        int idx = tid + it * 256;
        int mm = idx >> 2, kq = idx & 3;
        As[0][mm][kq * 4 + 0] = av[it].x;
        As[0][mm][kq * 4 + 1] = av[it].y;
        As[0][mm][kq * 4 + 2] = av[it].z;
        As[0][mm][kq * 4 + 3] = av[it].w;
        Bs[0][kq * 4 + 0][mm] = bv[it].x;
        Bs[0][kq * 4 + 1][mm] = bv[it].y;
        Bs[0][kq * 4 + 2][mm] = bv[it].z;
        Bs[0][kq * 4 + 3][mm] = bv[it].w;
    }
    __syncthreads();

    ull acc[8][4];
#pragma unroll
    for (int i = 0; i < 8; i++)
#pragma unroll
        for (int p = 0; p < 4; p++) acc[i][p] = 0ULL;

    int buf = 0;
    for (int kc = 0; kc < 8; kc++) {
        if (kc < 7) {
#pragma unroll
            for (int it = 0; it < 2; it++) {
                int idx = tid + it * 256;
                int mm = idx >> 2, kq = idx & 3;
                av[it] = *(const float4*)(A + (size_t)(m0 + mm) * HH +
                                          (kc + 1) * 16 + kq * 4);
                bv[it] = *(const float4*)(W + (size_t)mm * HH + (kc + 1) * 16 +
                                          kq * 4);
            }
        }
#pragma unroll
        for (int k = 0; k < 16; k++) {
            const ulonglong2* bp = (const ulonglong2*)&Bs[buf][k][n0];
            ulonglong2 u0 = bp[0], u1 = bp[1];
            ull ad[8];
#pragma unroll
            for (int i = 0; i < 8; i++) ad[i] = dup2(As[buf][mt + i][k]);
#pragma unroll
            for (int i = 0; i < 8; i++) {
                ffma2(acc[i][0], ad[i], u0.x);
                ffma2(acc[i][1], ad[i], u0.y);
                ffma2(acc[i][2], ad[i], u1.x);
                ffma2(acc[i][3], ad[i], u1.y);
            }
        }
        if (kc < 7) {
#pragma unroll
            for (int it = 0; it < 2; it++) {
                int idx = tid + it * 256;
                int mm = idx >> 2, kq = idx & 3;
                As[buf ^ 1][mm][kq * 4 + 0] = av[it].x;
                As[buf ^ 1][mm][kq * 4 + 1] = av[it].y;
                As[buf ^ 1][mm][kq * 4 + 2] = av[it].z;
                As[buf ^ 1][mm][kq * 4 + 3] = av[it].w;
                Bs[buf ^ 1][kq * 4 + 0][mm] = bv[it].x;
                Bs[buf ^ 1][kq * 4 + 1][mm] = bv[it].y;
                Bs[buf ^ 1][kq * 4 + 2][mm] = bv[it].z;
                Bs[buf ^ 1][kq * 4 + 3][mm] = bv[it].w;
            }
            __syncthreads();
            buf ^= 1;
        }
    }

    ull biasp[4];
#pragma unroll
    for (int p = 0; p < 4; p++) {
        float b0 = bih[n0 + 2 * p] + bhh[n0 + 2 * p];
        float b1 = bih[n0 + 2 * p + 1] + bhh[n0 + 2 * p + 1];
        biasp[p] = pack2(b0, b1);
    }
#pragma unroll
    for (int i = 0; i < 8; i++) {
        ull o0 = add2(acc[i][0], biasp[0]);
        ull o1 = add2(acc[i][1], biasp[1]);
        ull o2 = add2(acc[i][2], biasp[2]);
        ull o3 = add2(acc[i][3], biasp[3]);
        float* dst = xp + (size_t)(m0 + mt + i) * HH + n0;
        *(ulonglong2*)dst = make_ulonglong2(o0, o1);
        *(ulonglong2*)(dst + 4) = make_ulonglong2(o2, o3);
    }
}

// ---------------- recurrent scan (one layer) ----------------
// h[t] = relu(xp[t] + Whh @ h[t-1]); xp precomputed (includes biases).
// One CTA (128 threads, 4 warps) per batch row. Thread j holds the FULL
// row Whh[j, :] in 64 packed f32x2 registers and computes the complete dot
// product alone: no shuffles, no partial exchange, one __syncthreads per
// step over a 4-warp domain. Two independent CTAs co-resident per SM hide
// each other's stalls. xp comes through a distance-3 register ring.
__global__ void __launch_bounds__(128, 2)
rnn_scan(const float* __restrict__ xp, float* __restrict__ out_h,
         const float* __restrict__ Whh) {
    __shared__ __align__(16) float hbuf[2][HH];

    const int j = threadIdx.x;
    const int b = blockIdx.x;

    // full weight row, packed as 64 f32x2 pairs: w[i] = (W[j,2i], W[j,2i+1])
    ull w[64];
    {
        const ull* wp = (const ull*)(Whh + j * HH);
#pragma unroll
        for (int i = 0; i < 64; i++) w[i] = wp[i];
    }

    hbuf[0][j] = 0.f;  // h(-1) = 0

    const float* xptr = xp + (size_t)b * TT * HH + j;
    float* optr = out_h + (size_t)b * TT * HH + j;
    float xq0 = xptr[0];
    float xq1 = xptr[HH];
    float xq2 = xptr[2 * HH];
    const float* xf = xptr + 3 * HH;  // padded scratch: safe overrun
    __syncthreads();

    int buf = 0;
    for (int t = 0; t < TT; t++) {
        float xn = *xf;  // xp(t+3), lands 3 steps from now
        xf += HH;

        const ulonglong2* hp = (const ulonglong2*)hbuf[buf];
        ull a0 = 0ULL, a1 = 0ULL, a2 = 0ULL, a3 = 0ULL;
#pragma unroll
        for (int q = 0; q < 32; q += 4) {
            ulonglong2 u0 = hp[q];      // broadcast LDS.128: h[4q..4q+3]
            ulonglong2 u1 = hp[q + 1];
            ulonglong2 u2 = hp[q + 2];
            ulonglong2 u3 = hp[q + 3];
            ffma2(a0, u0.x, w[2 * q + 0]);
            ffma2(a0, u0.y, w[2 * q + 1]);
            ffma2(a1, u1.x, w[2 * q + 2]);
            ffma2(a1, u1.y, w[2 * q + 3]);
            ffma2(a2, u2.x, w[2 * q + 4]);
            ffma2(a2, u2.y, w[2 * q + 5]);
            ffma2(a3, u3.x, w[2 * q + 6]);
            ffma2(a3, u3.y, w[2 * q + 7]);
        }
        ull s = add2(add2(a0, a1), add2(a2, a3));
        float2 f = *(float2*)&s;
        float h = fmaxf(f.x + f.y + xq0, 0.f);

        hbuf[buf ^ 1][j] = h;
        optr[0] = h;  // warp writes 128B coalesced
        optr += HH;
        xq0 = xq1;
        xq1 = xq2;
        xq2 = xn;
        buf ^= 1;
        __syncthreads();
    }
}

// ---------------- FC on last timestep ----------------
__global__ void fc_kernel(const float* __restrict__ h,
                          const float* __restrict__ fcw,
                          const float* __restrict__ fcb,
                          float* __restrict__ out) {
    int b = blockIdx.x;
    int k = threadIdx.x;
    float v = h[(size_t)b * (TT * HH) + (TT - 1) * HH + k] * fcw[k];
#pragma unroll
    for (int o = 16; o > 0; o >>= 1) v += __shfl_down_sync(0xffffffffu, v, o);
    __shared__ float sred[4];
    if ((k & 31) == 0) sred[k >> 5] = v;
    __syncthreads();
    if (k == 0) out[b] = sred[0] + sred[1] + sred[2] + sred[3] + fcb[0];
}

extern "C" void kernel_launch(void* const* d_in, const int* in_sizes, int n_in,
                              void* d_out, int out_size) {
    const float* x    = (const float*)d_in[0];  // [B,T,I]
    const float* Wih0 = (const float*)d_in[1];  // [H,I]
    const float* WihL = (const float*)d_in[2];  // [L-1,H,H]
    const float* Whh  = (const float*)d_in[3];  // [L,H,H]
    const float* bih  = (const float*)d_in[4];  // [L,H]
    const float* bhh  = (const float*)d_in[5];  // [L,H]
    const float* fcw  = (const float*)d_in[6];  // [C,H]
    const float* fcb  = (const float*)d_in[7];  // [C]
    float* out = (float*)d_out;                 // [B,C] = [256,1]

    float *h0, *h1, *xpb;
    cudaGetSymbolAddress((void**)&h0, g_h0);
    cudaGetSymbolAddress((void**)&h1, g_h1);
    cudaGetSymbolAddress((void**)&xpb, g_xp);

    const int HW = HH * HH;
    // layer 0
    proj0_kernel<<<(MTOT * HH) / 256, 256>>>(x, Wih0, bih, bhh, xpb);
    rnn_scan<<<BB, 128>>>(xpb, h0, Whh + 0 * HW);
    // layer 1
    gemm_xp<<<MTOT / 128, 256>>>(h0, WihL + 0 * HW, bih + 1 * HH, bhh + 1 * HH,
                                 xpb);
    rnn_scan<<<BB, 128>>>(xpb, h1, Whh + 1 * HW);
    // layer 2
    gemm_xp<<<MTOT / 128, 256>>>(h1, WihL + 1 * HW, bih + 2 * HH, bhh + 2 * HH,
                                 xpb);
    rnn_scan<<<BB, 128>>>(xpb, h0, Whh + 2 * HW);
    // layer 3
    gemm_xp<<<MTOT / 128, 256>>>(h0, WihL + 2 * HW, bih + 3 * HH, bhh + 3 * HH,
                                 xpb);
    rnn_scan<<<BB, 128>>>(xpb, h1, Whh + 3 * HW);
    // fc
    fc_kernel<<<BB, HH>>>(h1, fcw, fcb, out);
}

// round 6
// speedup vs baseline: 1.7778x; 1.0011x over previous
#include <cuda_runtime.h>

#define BB 256
#define TT 1024
#define IDIM 2
#define HH 128
#define LL 4
#define MTOT (BB * TT)  // 262144

// Scratch (device globals: allocation-free). h ping-pong + xp stream.
// g_xp padded by 4 rows for the distance-3 register-ring prefetch overrun.
__device__ float g_h0[BB * TT * HH];
__device__ float g_h1[BB * TT * HH];
__device__ float g_xp[BB * TT * HH + 4 * HH];

typedef unsigned long long ull;

__device__ __forceinline__ void ffma2(ull& acc, ull a, ull b) {
    asm("fma.rn.f32x2 %0, %1, %2, %0;" : "+l"(acc) : "l"(a), "l"(b));
}
__device__ __forceinline__ ull add2(ull a, ull b) {
    ull d;
    asm("add.rn.f32x2 %0, %1, %2;" : "=l"(d) : "l"(a), "l"(b));
    return d;
}
__device__ __forceinline__ ull dup2(float a) {
    ull d;
    asm("mov.b64 %0, {%1, %1};" : "=l"(d) : "f"(a));
    return d;
}
__device__ __forceinline__ ull pack2(float x, float y) {
    ull d;
    asm("mov.b64 %0, {%1, %2};" : "=l"(d) : "f"(x), "f"(y));
    return d;
}

// ---------------- layer-0 input projection (I=2, trivial) ----------------
__global__ void proj0_kernel(const float* __restrict__ x,
                             const float* __restrict__ W0,
                             const float* __restrict__ bih,
                             const float* __restrict__ bhh,
                             float* __restrict__ xp) {
    int idx = blockIdx.x * 256 + threadIdx.x;
    int m = idx >> 7, j = idx & 127;
    float2 xv = *(const float2*)(x + m * 2);
    float2 w = *(const float2*)(W0 + j * 2);
    xp[idx] = fmaf(xv.x, w.x, fmaf(xv.y, w.y, bih[j] + bhh[j]));
}

// ---------------- input-projection GEMM for layers 1..3 ----------------
// xp[m, n] = sum_k A[m, k] * W[n, k] + bih[n] + bhh[n]
// M = 262144, N = K = 128. CTA tile 128(M) x 128(N), K staged in 16-chunks,
// double-buffered smem, 8x8 outputs/thread as f32x2 n-pairs.
__global__ void __launch_bounds__(256, 2)
gemm_xp(const float* __restrict__ A, const float* __restrict__ W,
        const float* __restrict__ bih, const float* __restrict__ bhh,
        float* __restrict__ xp) {
    __shared__ float As[2][128][17];
    __shared__ float Bs[2][16][132];

    const int tid = threadIdx.x;
    const int m0 = blockIdx.x * 128;
    const int tx = tid & 15, ty = tid >> 4;
    const int n0 = tx * 8, mt = ty * 8;

    float4 av[2], bv[2];
#pragma unroll
    for (int it = 0; it < 2; it++) {
        int idx = tid + it * 256;
        int mm = idx >> 2, kq = idx & 3;
        av[it] = *(const float4*)(A + (size_t)(m0 + mm) * HH + kq * 4);
        bv[it] = *(const float4*)(W + (size_t)mm * HH + kq * 4);
    }
#pragma unroll
    for (int it = 0; it < 2; it++) {
        int idx = tid + it * 256;
        int mm = idx >> 2, kq = idx & 3;
        As[0][mm][kq * 4 + 0] = av[it].x;
        As[0][mm][kq * 4 + 1] = av[it].y;
        As[0][mm][kq * 4 + 2] = av[it].z;
        As[0][mm][kq * 4 + 3] = av[it].w;
        Bs[0][kq * 4 + 0][mm] = bv[it].x;
        Bs[0][kq * 4 + 1][mm] = bv[it].y;
        Bs[0][kq * 4 + 2][mm] = bv[it].z;
        Bs[0][kq * 4 + 3][mm] = bv[it].w;
    }
    __syncthreads();

    ull acc[8][4];
#pragma unroll
    for (int i = 0; i < 8; i++)
#pragma unroll
        for (int p = 0; p < 4; p++) acc[i][p] = 0ULL;

    int buf = 0;
    for (int kc = 0; kc < 8; kc++) {
        if (kc < 7) {
#pragma unroll
            for (int it = 0; it < 2; it++) {
                int idx = tid + it * 256;
                int mm = idx >> 2, kq = idx & 3;
                av[it] = *(const float4*)(A + (size_t)(m0 + mm) * HH +
                                          (kc + 1) * 16 + kq * 4);
                bv[it] = *(const float4*)(W + (size_t)mm * HH + (kc + 1) * 16 +
                                          kq * 4);
            }
        }
#pragma unroll
        for (int k = 0; k < 16; k++) {
            const ulonglong2* bp = (const ulonglong2*)&Bs[buf][k][n0];
            ulonglong2 u0 = bp[0], u1 = bp[1];
            ull ad[8];
#pragma unroll
            for (int i = 0; i < 8; i++) ad[i] = dup2(As[buf][mt + i][k]);
#pragma unroll
            for (int i = 0; i < 8; i++) {
                ffma2(acc[i][0], ad[i], u0.x);
                ffma2(acc[i][1], ad[i], u0.y);
                ffma2(acc[i][2], ad[i], u1.x);
                ffma2(acc[i][3], ad[i], u1.y);
            }
        }
        if (kc < 7) {
#pragma unroll
            for (int it = 0; it < 2; it++) {
                int idx = tid + it * 256;
                int mm = idx >> 2, kq = idx & 3;
                As[buf ^ 1][mm][kq * 4 + 0] = av[it].x;
                As[buf ^ 1][mm][kq * 4 + 1] = av[it].y;
                As[buf ^ 1][mm][kq * 4 + 2] = av[it].z;
                As[buf ^ 1][mm][kq * 4 + 3] = av[it].w;
                Bs[buf ^ 1][kq * 4 + 0][mm] = bv[it].x;
                Bs[buf ^ 1][kq * 4 + 1][mm] = bv[it].y;
                Bs[buf ^ 1][kq * 4 + 2][mm] = bv[it].z;
                Bs[buf ^ 1][kq * 4 + 3][mm] = bv[it].w;
            }
            __syncthreads();
            buf ^= 1;
        }
    }

    ull biasp[4];
#pragma unroll
    for (int p = 0; p < 4; p++) {
        float b0 = bih[n0 + 2 * p] + bhh[n0 + 2 * p];
        float b1 = bih[n0 + 2 * p + 1] + bhh[n0 + 2 * p + 1];
        biasp[p] = pack2(b0, b1);
    }
#pragma unroll
    for (int i = 0; i < 8; i++) {
        ull o0 = add2(acc[i][0], biasp[0]);
        ull o1 = add2(acc[i][1], biasp[1]);
        ull o2 = add2(acc[i][2], biasp[2]);
        ull o3 = add2(acc[i][3], biasp[3]);
        float* dst = xp + (size_t)(m0 + mt + i) * HH + n0;
        *(ulonglong2*)dst = make_ulonglong2(o0, o1);
        *(ulonglong2*)(dst + 4) = make_ulonglong2(o2, o3);
    }
}

// ---------------- recurrent scan (one layer) ----------------
// h[t] = relu(xp[t] + Whh @ h[t-1]); xp precomputed (includes biases).
// One CTA (128 threads, 4 warps) per batch row. Thread j holds the FULL
// row Whh[j, :] in 64 packed f32x2 registers and computes the complete dot
// product alone: no shuffles, no partial exchange, one __syncthreads per
// step over a 4-warp domain. Two independent CTAs co-resident per SM hide
// each other's stalls. xp comes through a distance-3 register ring.
__global__ void __launch_bounds__(128, 2)
rnn_scan(const float* __restrict__ xp, float* __restrict__ out_h,
         const float* __restrict__ Whh) {
    __shared__ __align__(16) float hbuf[2][HH];

    const int j = threadIdx.x;
    const int b = blockIdx.x;

    // full weight row, packed as 64 f32x2 pairs: w[i] = (W[j,2i], W[j,2i+1])
    ull w[64];
    {
        const ull* wp = (const ull*)(Whh + j * HH);
#pragma unroll
        for (int i = 0; i < 64; i++) w[i] = wp[i];
    }

    hbuf[0][j] = 0.f;  // h(-1) = 0

    const float* xptr = xp + (size_t)b * TT * HH + j;
    float* optr = out_h + (size_t)b * TT * HH + j;
    float xq0 = xptr[0];
    float xq1 = xptr[HH];
    float xq2 = xptr[2 * HH];
    const float* xf = xptr + 3 * HH;  // padded scratch: safe overrun
    __syncthreads();

    int buf = 0;
    for (int t = 0; t < TT; t++) {
        float xn = *xf;  // xp(t+3), lands 3 steps from now
        xf += HH;

        const ulonglong2* hp = (const ulonglong2*)hbuf[buf];
        ull a0 = 0ULL, a1 = 0ULL, a2 = 0ULL, a3 = 0ULL;
#pragma unroll
        for (int q = 0; q < 32; q += 4) {
            ulonglong2 u0 = hp[q];      // broadcast LDS.128: h[4q..4q+3]
            ulonglong2 u1 = hp[q + 1];
            ulonglong2 u2 = hp[q + 2];
            ulonglong2 u3 = hp[q + 3];
            ffma2(a0, u0.x, w[2 * q + 0]);
            ffma2(a0, u0.y, w[2 * q + 1]);
            ffma2(a1, u1.x, w[2 * q + 2]);
            ffma2(a1, u1.y, w[2 * q + 3]);
            ffma2(a2, u2.x, w[2 * q + 4]);
            ffma2(a2, u2.y, w[2 * q + 5]);
            ffma2(a3, u3.x, w[2 * q + 6]);
            ffma2(a3, u3.y, w[2 * q + 7]);
        }
        ull s = add2(add2(a0, a1), add2(a2, a3));
        float2 f = *(float2*)&s;
        float h = fmaxf(f.x + f.y + xq0, 0.f);

        hbuf[buf ^ 1][j] = h;
        optr[0] = h;  // warp writes 128B coalesced
        optr += HH;
        xq0 = xq1;
        xq1 = xq2;
        xq2 = xn;
        buf ^= 1;
        __syncthreads();
    }
}

// ---------------- FC on last timestep ----------------
__global__ void fc_kernel(const float* __restrict__ h,
                          const float* __restrict__ fcw,
                          const float* __restrict__ fcb,
                          float* __restrict__ out) {
    int b = blockIdx.x;
    int k = threadIdx.x;
    float v = h[(size_t)b * (TT * HH) + (TT - 1) * HH + k] * fcw[k];
#pragma unroll
    for (int o = 16; o > 0; o >>= 1) v += __shfl_down_sync(0xffffffffu, v, o);
    __shared__ float sred[4];
    if ((k & 31) == 0) sred[k >> 5] = v;
    __syncthreads();
    if (k == 0) out[b] = sred[0] + sred[1] + sred[2] + sred[3] + fcb[0];
}

extern "C" void kernel_launch(void* const* d_in, const int* in_sizes, int n_in,
                              void* d_out, int out_size) {
    const float* x    = (const float*)d_in[0];  // [B,T,I]
    const float* Wih0 = (const float*)d_in[1];  // [H,I]
    const float* WihL = (const float*)d_in[2];  // [L-1,H,H]
    const float* Whh  = (const float*)d_in[3];  // [L,H,H]
    const float* bih  = (const float*)d_in[4];  // [L,H]
    const float* bhh  = (const float*)d_in[5];  // [L,H]
    const float* fcw  = (const float*)d_in[6];  // [C,H]
    const float* fcb  = (const float*)d_in[7];  // [C]
    float* out = (float*)d_out;                 // [B,C] = [256,1]

    float *h0, *h1, *xpb;
    cudaGetSymbolAddress((void**)&h0, g_h0);
    cudaGetSymbolAddress((void**)&h1, g_h1);
    cudaGetSymbolAddress((void**)&xpb, g_xp);

    const int HW = HH * HH;
    // layer 0
    proj0_kernel<<<(MTOT * HH) / 256, 256>>>(x, Wih0, bih, bhh, xpb);
    rnn_scan<<<BB, 128>>>(xpb, h0, Whh + 0 * HW);
    // layer 1
    gemm_xp<<<MTOT / 128, 256>>>(h0, WihL + 0 * HW, bih + 1 * HH, bhh + 1 * HH,
                                 xpb);
    rnn_scan<<<BB, 128>>>(xpb, h1, Whh + 1 * HW);
    // layer 2
    gemm_xp<<<MTOT / 128, 256>>>(h1, WihL + 1 * HW, bih + 2 * HH, bhh + 2 * HH,
                                 xpb);
    rnn_scan<<<BB, 128>>>(xpb, h0, Whh + 2 * HW);
    // layer 3
    gemm_xp<<<MTOT / 128, 256>>>(h0, WihL + 2 * HW, bih + 3 * HH, bhh + 3 * HH,
                                 xpb);
    rnn_scan<<<BB, 128>>>(xpb, h1, Whh + 3 * HW);
    // fc
    fc_kernel<<<BB, HH>>>(h1, fcw, fcb, out);
}